// round 4
// baseline (speedup 1.0000x reference)
#include <cuda_runtime.h>
#include <math.h>
#include <limits.h>

#define EPSV 1e-12f
#define DIMS 768
#define MAXM (131072)
#define KMAX 8
#define NBLK_PART 128
#define TPB 256

// Scratch (no cudaMalloc allowed)
__device__ float g_scores[MAXM];
__device__ float g_cand_val[NBLK_PART * KMAX];
__device__ int   g_cand_idx[NBLK_PART * KMAX];

// Ordering consistent with jax.lax.top_k: higher value first, lower index on ties.
__device__ __forceinline__ bool better(float v1, int i1, float v2, int i2) {
    return (v1 > v2) || (v1 == v2 && i1 < i2);
}

// ---------------------------------------------------------------------------
// Kernel 1: fused scoring, one warp per memory row.
// ---------------------------------------------------------------------------
__global__ void __launch_bounds__(TPB)
score_kernel(const float* __restrict__ q,
             const float* __restrict__ loc,
             const float* __restrict__ feats,
             const float* __restrict__ locs,
             const float* __restrict__ meta,
             int M)
{
    __shared__ __align__(16) float s_q[DIMS];
    __shared__ float s_wsum[TPB / 32];
    __shared__ float s_qn;
    __shared__ float s_loc0, s_loc1;

    // Stage query into shared, accumulate |q|^2
    float part = 0.f;
    for (int i = threadIdx.x; i < DIMS; i += TPB) {
        float v = q[i];
        s_q[i] = v;
        part += v * v;
    }
    #pragma unroll
    for (int o = 16; o; o >>= 1) part += __shfl_xor_sync(0xffffffffu, part, o);

    const int wid  = threadIdx.x >> 5;
    const int lane = threadIdx.x & 31;
    if (lane == 0) s_wsum[wid] = part;
    __syncthreads();
    if (threadIdx.x == 0) {
        float s = 0.f;
        #pragma unroll
        for (int w = 0; w < TPB / 32; w++) s += s_wsum[w];
        s_qn = fmaxf(sqrtf(s), EPSV);
        s_loc0 = loc[0];
        s_loc1 = loc[1];
    }
    __syncthreads();

    const int row = blockIdx.x * (TPB / 32) + wid;
    if (row >= M) return;

    const float4* __restrict__ rp = reinterpret_cast<const float4*>(feats + (size_t)row * DIMS);
    const float4* __restrict__ qp = reinterpret_cast<const float4*>(s_q);

    float dot = 0.f, ss = 0.f;
    #pragma unroll
    for (int i = 0; i < DIMS / 128; i++) {          // 6 iterations of float4
        float4 a = rp[lane + 32 * i];
        float4 b = qp[lane + 32 * i];
        dot += a.x * b.x + a.y * b.y + a.z * b.z + a.w * b.w;
        ss  += a.x * a.x + a.y * a.y + a.z * a.z + a.w * a.w;
    }
    #pragma unroll
    for (int o = 16; o; o >>= 1) {
        dot += __shfl_xor_sync(0xffffffffu, dot, o);
        ss  += __shfl_xor_sync(0xffffffffu, ss,  o);
    }

    if (lane == 0) {
        float sim = dot / (fmaxf(sqrtf(ss), EPSV) * s_qn);

        float dx = locs[2 * row + 0] - s_loc0;
        float dy = locs[2 * row + 1] - s_loc1;
        float spatial = 1.f / (1.f + sqrtf(dx * dx + dy * dy));

        float strength = meta[4 * row + 0];
        float ts       = meta[4 * row + 1];
        // exp(-(3600 - ts)/3600) == exp(ts/3600 - 1)
        float temporal = expf(ts * (1.f / 3600.f) - 1.f);

        g_scores[row] = (0.5f * sim + 0.3f * spatial + 0.2f * temporal) * strength;
    }
}

// ---------------------------------------------------------------------------
// Kernel 2: per-block partial top-k over g_scores.
// ---------------------------------------------------------------------------
__global__ void __launch_bounds__(TPB)
topk_partial(int M, int k)
{
    __shared__ float s_val[TPB * KMAX];
    __shared__ int   s_idx[TPB * KMAX];
    __shared__ float s_rv[TPB / 32];
    __shared__ int   s_ri[TPB / 32];
    __shared__ int   s_rp[TPB / 32];

    float lv[KMAX];
    int   li[KMAX];
    #pragma unroll
    for (int j = 0; j < KMAX; j++) { lv[j] = -INFINITY; li[j] = INT_MAX; }

    const int chunk = (M + gridDim.x - 1) / gridDim.x;
    const int beg = blockIdx.x * chunk;
    const int end = min(M, beg + chunk);

    for (int i = beg + threadIdx.x; i < end; i += TPB) {
        float v = g_scores[i];
        if (better(v, i, lv[k - 1], li[k - 1])) {
            int j = k - 1;
            while (j > 0 && better(v, i, lv[j - 1], li[j - 1])) {
                lv[j] = lv[j - 1]; li[j] = li[j - 1]; --j;
            }
            lv[j] = v; li[j] = i;
        }
    }

    for (int j = 0; j < k; j++) {
        s_val[threadIdx.x * k + j] = lv[j];
        s_idx[threadIdx.x * k + j] = li[j];
    }
    __syncthreads();

    const int total = TPB * k;
    const int wid  = threadIdx.x >> 5;
    const int lane = threadIdx.x & 31;

    for (int sel = 0; sel < k; sel++) {
        float bv = -INFINITY; int bi = INT_MAX; int bp = -1;
        for (int p = threadIdx.x; p < total; p += TPB) {
            if (better(s_val[p], s_idx[p], bv, bi)) { bv = s_val[p]; bi = s_idx[p]; bp = p; }
        }
        #pragma unroll
        for (int o = 16; o; o >>= 1) {
            float ov = __shfl_xor_sync(0xffffffffu, bv, o);
            int   oi = __shfl_xor_sync(0xffffffffu, bi, o);
            int   op = __shfl_xor_sync(0xffffffffu, bp, o);
            if (better(ov, oi, bv, bi)) { bv = ov; bi = oi; bp = op; }
        }
        if (lane == 0) { s_rv[wid] = bv; s_ri[wid] = bi; s_rp[wid] = bp; }
        __syncthreads();
        if (threadIdx.x == 0) {
            bv = s_rv[0]; bi = s_ri[0]; bp = s_rp[0];
            #pragma unroll
            for (int w = 1; w < TPB / 32; w++)
                if (better(s_rv[w], s_ri[w], bv, bi)) { bv = s_rv[w]; bi = s_ri[w]; bp = s_rp[w]; }
            g_cand_val[blockIdx.x * k + sel] = bv;
            g_cand_idx[blockIdx.x * k + sel] = bi;
            if (bp >= 0) { s_val[bp] = -INFINITY; s_idx[bp] = INT_MAX; }
        }
        __syncthreads();
    }
}

// ---------------------------------------------------------------------------
// Kernel 3: final top-k over block candidates; writes [scores | indices].
// ---------------------------------------------------------------------------
__global__ void __launch_bounds__(TPB)
topk_final(int ncand, int k, float* __restrict__ out)
{
    __shared__ float s_val[NBLK_PART * KMAX];
    __shared__ int   s_idx[NBLK_PART * KMAX];
    __shared__ float s_rv[TPB / 32];
    __shared__ int   s_ri[TPB / 32];
    __shared__ int   s_rp[TPB / 32];

    for (int p = threadIdx.x; p < ncand; p += TPB) {
        s_val[p] = g_cand_val[p];
        s_idx[p] = g_cand_idx[p];
    }
    __syncthreads();

    const int wid  = threadIdx.x >> 5;
    const int lane = threadIdx.x & 31;

    for (int sel = 0; sel < k; sel++) {
        float bv = -INFINITY; int bi = INT_MAX; int bp = -1;
        for (int p = threadIdx.x; p < ncand; p += TPB) {
            if (better(s_val[p], s_idx[p], bv, bi)) { bv = s_val[p]; bi = s_idx[p]; bp = p; }
        }
        #pragma unroll
        for (int o = 16; o; o >>= 1) {
            float ov = __shfl_xor_sync(0xffffffffu, bv, o);
            int   oi = __shfl_xor_sync(0xffffffffu, bi, o);
            int   op = __shfl_xor_sync(0xffffffffu, bp, o);
            if (better(ov, oi, bv, bi)) { bv = ov; bi = oi; bp = op; }
        }
        if (lane == 0) { s_rv[wid] = bv; s_ri[wid] = bi; s_rp[wid] = bp; }
        __syncthreads();
        if (threadIdx.x == 0) {
            bv = s_rv[0]; bi = s_ri[0]; bp = s_rp[0];
            #pragma unroll
            for (int w = 1; w < TPB / 32; w++)
                if (better(s_rv[w], s_ri[w], bv, bi)) { bv = s_rv[w]; bi = s_ri[w]; bp = s_rp[w]; }
            out[sel]     = bv;              // top_scores
            out[k + sel] = (float)bi;       // top_indices (exact in fp32 for idx < 2^24)
            if (bp >= 0) { s_val[bp] = -INFINITY; s_idx[bp] = INT_MAX; }
        }
        __syncthreads();
    }
}

// ---------------------------------------------------------------------------
// Launch
// ---------------------------------------------------------------------------
extern "C" void kernel_launch(void* const* d_in, const int* in_sizes, int n_in,
                              void* d_out, int out_size)
{
    const float* q     = (const float*)d_in[0];   // (768,)
    const float* loc   = (const float*)d_in[1];   // (2,)
    const float* feats = (const float*)d_in[2];   // (M, 768)
    const float* locs  = (const float*)d_in[3];   // (M, 2)
    const float* meta  = (const float*)d_in[4];   // (M, 4)
    float* out = (float*)d_out;                   // [k scores | k indices]

    int M = in_sizes[2] / DIMS;
    if (M > MAXM) M = MAXM;
    int k = out_size / 2;
    if (k < 1) k = 1;
    if (k > KMAX) k = KMAX;

    const int warps_per_block = TPB / 32;
    const int nblk_score = (M + warps_per_block - 1) / warps_per_block;

    score_kernel<<<nblk_score, TPB>>>(q, loc, feats, locs, meta, M);
    topk_partial<<<NBLK_PART, TPB>>>(M, k);
    topk_final<<<1, TPB>>>(NBLK_PART * k, k, out);
}

// round 5
// speedup vs baseline: 1.0677x; 1.0677x over previous
#include <cuda_runtime.h>
#include <math.h>
#include <limits.h>

#define EPSV 1e-12f
#define DIMS 768
#define MAXM (131072)
#define KMAX 8
#define NBLK_PART 128
#define TPB 256

// Scratch (no cudaMalloc allowed)
__device__ float g_scores[MAXM];
__device__ float g_cand_val[NBLK_PART * KMAX];
__device__ int   g_cand_idx[NBLK_PART * KMAX];

// Ordering consistent with jax.lax.top_k: higher value first, lower index on ties.
__device__ __forceinline__ bool better(float v1, int i1, float v2, int i2) {
    return (v1 > v2) || (v1 == v2 && i1 < i2);
}

// ---------------------------------------------------------------------------
// Kernel 1: fused scoring, one warp per memory row. BARRIER-FREE.
// q-norm is computed redundantly per warp (free: q is already being loaded
// for the dot product), so there is no shared staging and no __syncthreads.
// ---------------------------------------------------------------------------
__global__ void __launch_bounds__(TPB)
score_kernel(const float4* __restrict__ q4,
             const float*  __restrict__ loc,
             const float4* __restrict__ feats4,
             const float2* __restrict__ locs2,
             const float4* __restrict__ meta4,
             int M)
{
    const int wid  = threadIdx.x >> 5;
    const int lane = threadIdx.x & 31;
    const int row  = blockIdx.x * (TPB / 32) + wid;
    if (row >= M) return;

    // Issue epilogue loads early so their latency hides under the feats stream.
    float2 lrow = make_float2(0.f, 0.f);
    float4 mrow = make_float4(0.f, 0.f, 0.f, 0.f);
    float  l0 = 0.f, l1 = 0.f;
    if (lane == 0) {
        lrow = __ldg(locs2 + row);
        mrow = __ldg(meta4 + row);
        l0 = __ldg(loc);
        l1 = __ldg(loc + 1);
    }

    const float4* __restrict__ rp = feats4 + (size_t)row * (DIMS / 4);

    // Batch all 6 row loads up-front (MLP=6/warp), streaming hint (read-once).
    float4 a0 = __ldcs(rp + lane + 32 * 0);
    float4 a1 = __ldcs(rp + lane + 32 * 1);
    float4 a2 = __ldcs(rp + lane + 32 * 2);
    float4 a3 = __ldcs(rp + lane + 32 * 3);
    float4 a4 = __ldcs(rp + lane + 32 * 4);
    float4 a5 = __ldcs(rp + lane + 32 * 5);

    float dot = 0.f, ss = 0.f, qq = 0.f;
    {
        float4 b;
        b = __ldg(q4 + lane + 32 * 0);
        dot += a0.x*b.x + a0.y*b.y + a0.z*b.z + a0.w*b.w;
        ss  += a0.x*a0.x + a0.y*a0.y + a0.z*a0.z + a0.w*a0.w;
        qq  += b.x*b.x + b.y*b.y + b.z*b.z + b.w*b.w;
        b = __ldg(q4 + lane + 32 * 1);
        dot += a1.x*b.x + a1.y*b.y + a1.z*b.z + a1.w*b.w;
        ss  += a1.x*a1.x + a1.y*a1.y + a1.z*a1.z + a1.w*a1.w;
        qq  += b.x*b.x + b.y*b.y + b.z*b.z + b.w*b.w;
        b = __ldg(q4 + lane + 32 * 2);
        dot += a2.x*b.x + a2.y*b.y + a2.z*b.z + a2.w*b.w;
        ss  += a2.x*a2.x + a2.y*a2.y + a2.z*a2.z + a2.w*a2.w;
        qq  += b.x*b.x + b.y*b.y + b.z*b.z + b.w*b.w;
        b = __ldg(q4 + lane + 32 * 3);
        dot += a3.x*b.x + a3.y*b.y + a3.z*b.z + a3.w*b.w;
        ss  += a3.x*a3.x + a3.y*a3.y + a3.z*a3.z + a3.w*a3.w;
        qq  += b.x*b.x + b.y*b.y + b.z*b.z + b.w*b.w;
        b = __ldg(q4 + lane + 32 * 4);
        dot += a4.x*b.x + a4.y*b.y + a4.z*b.z + a4.w*b.w;
        ss  += a4.x*a4.x + a4.y*a4.y + a4.z*a4.z + a4.w*a4.w;
        qq  += b.x*b.x + b.y*b.y + b.z*b.z + b.w*b.w;
        b = __ldg(q4 + lane + 32 * 5);
        dot += a5.x*b.x + a5.y*b.y + a5.z*b.z + a5.w*b.w;
        ss  += a5.x*a5.x + a5.y*a5.y + a5.z*a5.z + a5.w*a5.w;
        qq  += b.x*b.x + b.y*b.y + b.z*b.z + b.w*b.w;
    }

    #pragma unroll
    for (int o = 16; o; o >>= 1) {
        dot += __shfl_xor_sync(0xffffffffu, dot, o);
        ss  += __shfl_xor_sync(0xffffffffu, ss,  o);
        qq  += __shfl_xor_sync(0xffffffffu, qq,  o);
    }

    if (lane == 0) {
        float qn = fmaxf(sqrtf(qq), EPSV);
        float mn = fmaxf(sqrtf(ss), EPSV);
        float sim = dot / (mn * qn);

        float dx = lrow.x - l0;
        float dy = lrow.y - l1;
        float spatial = 1.f / (1.f + sqrtf(dx * dx + dy * dy));

        float strength = mrow.x;
        float ts       = mrow.y;
        // exp(-(3600 - ts)/3600) == exp(ts/3600 - 1)
        float temporal = expf(ts * (1.f / 3600.f) - 1.f);

        g_scores[row] = (0.5f * sim + 0.3f * spatial + 0.2f * temporal) * strength;
    }
}

// ---------------------------------------------------------------------------
// Kernel 2: per-block partial top-k over g_scores.
// ---------------------------------------------------------------------------
__global__ void __launch_bounds__(TPB)
topk_partial(int M, int k)
{
    __shared__ float s_val[TPB * KMAX];
    __shared__ int   s_idx[TPB * KMAX];
    __shared__ float s_rv[TPB / 32];
    __shared__ int   s_ri[TPB / 32];
    __shared__ int   s_rp[TPB / 32];

    float lv[KMAX];
    int   li[KMAX];
    #pragma unroll
    for (int j = 0; j < KMAX; j++) { lv[j] = -INFINITY; li[j] = INT_MAX; }

    const int chunk = (M + gridDim.x - 1) / gridDim.x;
    const int beg = blockIdx.x * chunk;
    const int end = min(M, beg + chunk);

    for (int i = beg + threadIdx.x; i < end; i += TPB) {
        float v = g_scores[i];
        if (better(v, i, lv[k - 1], li[k - 1])) {
            int j = k - 1;
            while (j > 0 && better(v, i, lv[j - 1], li[j - 1])) {
                lv[j] = lv[j - 1]; li[j] = li[j - 1]; --j;
            }
            lv[j] = v; li[j] = i;
        }
    }

    for (int j = 0; j < k; j++) {
        s_val[threadIdx.x * k + j] = lv[j];
        s_idx[threadIdx.x * k + j] = li[j];
    }
    __syncthreads();

    const int total = TPB * k;
    const int wid  = threadIdx.x >> 5;
    const int lane = threadIdx.x & 31;

    for (int sel = 0; sel < k; sel++) {
        float bv = -INFINITY; int bi = INT_MAX; int bp = -1;
        for (int p = threadIdx.x; p < total; p += TPB) {
            if (better(s_val[p], s_idx[p], bv, bi)) { bv = s_val[p]; bi = s_idx[p]; bp = p; }
        }
        #pragma unroll
        for (int o = 16; o; o >>= 1) {
            float ov = __shfl_xor_sync(0xffffffffu, bv, o);
            int   oi = __shfl_xor_sync(0xffffffffu, bi, o);
            int   op = __shfl_xor_sync(0xffffffffu, bp, o);
            if (better(ov, oi, bv, bi)) { bv = ov; bi = oi; bp = op; }
        }
        if (lane == 0) { s_rv[wid] = bv; s_ri[wid] = bi; s_rp[wid] = bp; }
        __syncthreads();
        if (threadIdx.x == 0) {
            bv = s_rv[0]; bi = s_ri[0]; bp = s_rp[0];
            #pragma unroll
            for (int w = 1; w < TPB / 32; w++)
                if (better(s_rv[w], s_ri[w], bv, bi)) { bv = s_rv[w]; bi = s_ri[w]; bp = s_rp[w]; }
            g_cand_val[blockIdx.x * k + sel] = bv;
            g_cand_idx[blockIdx.x * k + sel] = bi;
            if (bp >= 0) { s_val[bp] = -INFINITY; s_idx[bp] = INT_MAX; }
        }
        __syncthreads();
    }
}

// ---------------------------------------------------------------------------
// Kernel 3: final top-k over block candidates; writes [scores | indices].
// ---------------------------------------------------------------------------
__global__ void __launch_bounds__(TPB)
topk_final(int ncand, int k, float* __restrict__ out)
{
    __shared__ float s_val[NBLK_PART * KMAX];
    __shared__ int   s_idx[NBLK_PART * KMAX];
    __shared__ float s_rv[TPB / 32];
    __shared__ int   s_ri[TPB / 32];
    __shared__ int   s_rp[TPB / 32];

    for (int p = threadIdx.x; p < ncand; p += TPB) {
        s_val[p] = g_cand_val[p];
        s_idx[p] = g_cand_idx[p];
    }
    __syncthreads();

    const int wid  = threadIdx.x >> 5;
    const int lane = threadIdx.x & 31;

    for (int sel = 0; sel < k; sel++) {
        float bv = -INFINITY; int bi = INT_MAX; int bp = -1;
        for (int p = threadIdx.x; p < ncand; p += TPB) {
            if (better(s_val[p], s_idx[p], bv, bi)) { bv = s_val[p]; bi = s_idx[p]; bp = p; }
        }
        #pragma unroll
        for (int o = 16; o; o >>= 1) {
            float ov = __shfl_xor_sync(0xffffffffu, bv, o);
            int   oi = __shfl_xor_sync(0xffffffffu, bi, o);
            int   op = __shfl_xor_sync(0xffffffffu, bp, o);
            if (better(ov, oi, bv, bi)) { bv = ov; bi = oi; bp = op; }
        }
        if (lane == 0) { s_rv[wid] = bv; s_ri[wid] = bi; s_rp[wid] = bp; }
        __syncthreads();
        if (threadIdx.x == 0) {
            bv = s_rv[0]; bi = s_ri[0]; bp = s_rp[0];
            #pragma unroll
            for (int w = 1; w < TPB / 32; w++)
                if (better(s_rv[w], s_ri[w], bv, bi)) { bv = s_rv[w]; bi = s_ri[w]; bp = s_rp[w]; }
            out[sel]     = bv;              // top_scores
            out[k + sel] = (float)bi;       // top_indices (exact in fp32 for idx < 2^24)
            if (bp >= 0) { s_val[bp] = -INFINITY; s_idx[bp] = INT_MAX; }
        }
        __syncthreads();
    }
}

// ---------------------------------------------------------------------------
// Launch
// ---------------------------------------------------------------------------
extern "C" void kernel_launch(void* const* d_in, const int* in_sizes, int n_in,
                              void* d_out, int out_size)
{
    const float* q     = (const float*)d_in[0];   // (768,)
    const float* loc   = (const float*)d_in[1];   // (2,)
    const float* feats = (const float*)d_in[2];   // (M, 768)
    const float* locs  = (const float*)d_in[3];   // (M, 2)
    const float* meta  = (const float*)d_in[4];   // (M, 4)
    float* out = (float*)d_out;                   // [k scores | k indices]

    int M = in_sizes[2] / DIMS;
    if (M > MAXM) M = MAXM;
    int k = out_size / 2;
    if (k < 1) k = 1;
    if (k > KMAX) k = KMAX;

    const int warps_per_block = TPB / 32;
    const int nblk_score = (M + warps_per_block - 1) / warps_per_block;

    score_kernel<<<nblk_score, TPB>>>((const float4*)q, loc,
                                      (const float4*)feats,
                                      (const float2*)locs,
                                      (const float4*)meta, M);
    topk_partial<<<NBLK_PART, TPB>>>(M, k);
    topk_final<<<1, TPB>>>(NBLK_PART * k, k, out);
}